// round 13
// baseline (speedup 1.0000x reference)
#include <cuda_runtime.h>

#define IN_CH 16
#define OUT_CH 64
#define HDIM 32
#define WDIM 32
#define NB 8
#define KHW 9
#define F (IN_CH * KHW)      // 144
#define OCG 8                // out channels per block
#define ROWS 2               // output rows per block
#define NQ 8                 // column quads (4 cols per thread)
#define CSPLIT 8             // input-channel split
#define CPT 2                // channels per thread
#define TPB 128              // 8 quads * 2 rows * 8 cs
#define TW 34                // tile width with halo
#define PSP 36               // ps inner stride (floats, 16B-aligned)

__global__ __launch_bounds__(TPB, 7) void normdist_kernel(
    const float* __restrict__ x,      // (8,16,32,32)
    const float* __restrict__ weight, // (64,144)
    const float* __restrict__ bias,   // (64)
    float* __restrict__ out)          // (8,64,32,32)
{
    const int og  = blockIdx.x;            // 0..7 out-channel group
    const int rg  = blockIdx.y;            // 0..15 row group
    const int n   = blockIdx.z;            // 0..7 batch
    const int tid = threadIdx.x;
    const int q   = tid & 7;               // 0..7 column quad (cols 4q..4q+3)
    const int r   = (tid >> 3) & 1;        // 0..1 row
    const int cs  = tid >> 4;              // 0..7 channel pair (warp covers cs 0/1)

    const int row0 = rg * ROWS;

    __shared__ float xs[IN_CH][ROWS + 2][TW];               // 8704 B
    __shared__ __align__(16) float wT[F][OCG];              // 4608 B
    __shared__ __align__(16) float ps[CSPLIT - 1][ROWS][NQ][PSP]; // 16128 B

    // ---- transposed weights: wT[f][oo] = weight[(og*8+oo)*144 + f]
    {
        const float* wsrc = weight + og * OCG * F;
        #pragma unroll
        for (int k = 0; k < 9; k++) {          // 9*128 = 1152 exactly
            int idx = tid + k * TPB;
            int oo = idx & (OCG - 1);
            int f  = idx >> 3;
            wT[f][oo] = wsrc[oo * F + f];
        }
    }

    // ---- x tile with halo; shift-only indexing (64 (c,rr) pairs x 2 lanes)
    {
        const float* xn = x + (size_t)n * IN_CH * HDIM * WDIM;
        const int pair = tid >> 1;             // 0..63
        const int l2   = tid & 1;
        const int c    = pair >> 2;            // 0..15
        const int rr   = pair & 3;             // 0..3
        const int gr   = row0 - 1 + rr;
        const bool rok = (gr >= 0) && (gr < HDIM);
        const float* src = xn + (c * HDIM + gr) * WDIM;
        float* dst = &xs[c][rr][0];
        #pragma unroll
        for (int e = 0; e < 17; e++) {         // 17*2 = 34
            int cc = l2 + e * 2;
            int gc = cc - 1;
            float v = 0.0f;
            if (rok && gc >= 0 && gc < WDIM) v = src[gc];
            dst[cc] = v;
        }
    }
    __syncthreads();

    // 4 columns x 8 out-channels of accumulators
    float acc[4][OCG];
    #pragma unroll
    for (int k = 0; k < 4; k++)
        #pragma unroll
        for (int o = 0; o < OCG; o++) acc[k][o] = 0.0f;

    const float* x0 = &xs[cs * CPT    ][r][4 * q];
    const float* x1 = &xs[cs * CPT + 1][r][4 * q];
    const float* wbase = &wT[cs * CPT * KHW][0];

    #pragma unroll
    for (int i = 0; i < 3; i++) {
        // 6-wide padded-row segments for both channels (3x LDS.64 each)
        float p0[6], p1[6];
        #pragma unroll
        for (int e = 0; e < 3; e++) {
            float2 a = *reinterpret_cast<const float2*>(x0 + i * TW + 2 * e);
            float2 b = *reinterpret_cast<const float2*>(x1 + i * TW + 2 * e);
            p0[2 * e] = a.x; p0[2 * e + 1] = a.y;
            p1[2 * e] = b.x; p1[2 * e + 1] = b.y;
        }

        #pragma unroll
        for (int j = 0; j < 3; j++) {
            // weights for tap (i,j) of ch0 and ch1: 4x LDS.128
            const float4* w0p = reinterpret_cast<const float4*>(
                wbase + (i * 3 + j) * OCG);
            const float4* w1p = reinterpret_cast<const float4*>(
                wbase + (KHW + i * 3 + j) * OCG);
            float4 wa0 = w0p[0], wb0 = w0p[1];
            float4 wa1 = w1p[0], wb1 = w1p[1];
            const float w0[OCG] = {wa0.x, wa0.y, wa0.z, wa0.w,
                                   wb0.x, wb0.y, wb0.z, wb0.w};
            const float w1[OCG] = {wa1.x, wa1.y, wa1.z, wa1.w,
                                   wb1.x, wb1.y, wb1.z, wb1.w};

            #pragma unroll
            for (int k = 0; k < 4; k++) {
                const float pa = p0[j + k];   // ch0 tap for col 4q+k
                const float pb = p1[j + k];   // ch1 tap for col 4q+k
                #pragma unroll
                for (int o = 0; o < OCG; o++) {
                    // FMNMX3: max(max(acc, |pa-w0|), |pb-w1|)
                    acc[k][o] = fmaxf(fmaxf(acc[k][o], fabsf(pa - w0[o])),
                                      fabsf(pb - w1[o]));
                }
            }
        }
    }

    // ---- reduce the 8 channel-pairs
    if (cs > 0) {
        float* p = &ps[cs - 1][r][q][0];
        #pragma unroll
        for (int k = 0; k < 4; k++) {
            float4 v4 = make_float4(acc[k][0], acc[k][1], acc[k][2], acc[k][3]);
            float4 v4b = make_float4(acc[k][4], acc[k][5], acc[k][6], acc[k][7]);
            *reinterpret_cast<float4*>(p + k * 8)     = v4;
            *reinterpret_cast<float4*>(p + k * 8 + 4) = v4b;
        }
    }
    __syncthreads();

    if (cs == 0) {
        // fold in 7 partial sets (float4 loads, FMNMX3 pairs)
        #pragma unroll
        for (int g = 0; g < CSPLIT - 1; g++) {
            const float* p = &ps[g][r][q][0];
            #pragma unroll
            for (int k = 0; k < 4; k++) {
                float4 v4  = *reinterpret_cast<const float4*>(p + k * 8);
                float4 v4b = *reinterpret_cast<const float4*>(p + k * 8 + 4);
                acc[k][0] = fmaxf(acc[k][0], v4.x);
                acc[k][1] = fmaxf(acc[k][1], v4.y);
                acc[k][2] = fmaxf(acc[k][2], v4.z);
                acc[k][3] = fmaxf(acc[k][3], v4.w);
                acc[k][4] = fmaxf(acc[k][4], v4b.x);
                acc[k][5] = fmaxf(acc[k][5], v4b.y);
                acc[k][6] = fmaxf(acc[k][6], v4b.z);
                acc[k][7] = fmaxf(acc[k][7], v4b.w);
            }
        }

        const int orow = row0 + r;
        float* outp = out + (((size_t)n * OUT_CH + og * OCG) * HDIM + orow) * WDIM + 4 * q;
        #pragma unroll
        for (int o = 0; o < OCG; o++) {
            const float bi = __ldg(&bias[og * OCG + o]);
            float4 res = make_float4(acc[0][o] + bi, acc[1][o] + bi,
                                     acc[2][o] + bi, acc[3][o] + bi);
            *reinterpret_cast<float4*>(outp + (size_t)o * HDIM * WDIM) = res;
        }
    }
}

extern "C" void kernel_launch(void* const* d_in, const int* in_sizes, int n_in,
                              void* d_out, int out_size) {
    const float* x      = (const float*)d_in[0];
    const float* weight = (const float*)d_in[1];
    const float* bias   = (const float*)d_in[2];
    float* out          = (float*)d_out;

    dim3 grid(OUT_CH / OCG, HDIM / ROWS, NB);   // (8, 16, 8) = 1024 blocks
    normdist_kernel<<<grid, TPB>>>(x, weight, bias, out);
}